// round 1
// baseline (speedup 1.0000x reference)
#include <cuda_runtime.h>
#include <cstdint>

// Problem constants
#define DIMM   2048
#define HN     16
#define HDIM   128
#define BB     2
#define NN     2048
#define E3     (3 * HN * HDIM)      // 6144
#define MROWS  (BB * NN)            // 4096
#define EPSV   1e-5f
#define QSCALE 0.08838834764831845f // 1/sqrt(128)

// ---------------- scratch (static device arrays; no allocation) -------------
__device__ float g_qkv[(size_t)MROWS * E3];            // [4096, 6144]  ~100.7 MB
__device__ float g_q[(size_t)BB * HN * NN * HDIM];     // [B,H,N,HD]    32 MB
__device__ float g_k[(size_t)BB * HN * NN * HDIM];
__device__ float g_v[(size_t)BB * HN * NN * HDIM];
__device__ float g_ao[(size_t)MROWS * (HN * HDIM)];    // [4096, 2048]  33.5 MB

// ============================================================================
// SGEMM: C[m,n] = sum_k A[m,k] * B[n,k]   (both row-major, K contiguous)
// Tile 128x128, BK=8, 256 threads, 8x8 microtile.
// ============================================================================
__global__ void __launch_bounds__(256, 2) sgemm_tn(
    const float* __restrict__ A, const float* __restrict__ B,
    float* __restrict__ C, int M, int N, int K)
{
    __shared__ float As[8][128];
    __shared__ float Bs[8][128];

    const int tid = threadIdx.x;
    const int bm = blockIdx.y * 128;
    const int bn = blockIdx.x * 128;
    const int tx = tid & 15;   // col group
    const int ty = tid >> 4;   // row group

    // gmem load mapping: each thread loads one float4 of A tile and one of B tile
    const int lr = tid >> 1;            // row within tile 0..127
    const int lk = (tid & 1) << 2;      // k offset 0 or 4

    const float* Aptr = A + (size_t)(bm + lr) * K + lk;
    const float* Bptr = B + (size_t)(bn + lr) * K + lk;

    float acc[8][8];
#pragma unroll
    for (int i = 0; i < 8; i++)
#pragma unroll
        for (int j = 0; j < 8; j++) acc[i][j] = 0.f;

    for (int k0 = 0; k0 < K; k0 += 8) {
        float4 av = *(const float4*)(Aptr + k0);
        float4 bv = *(const float4*)(Bptr + k0);
        __syncthreads();
        As[lk + 0][lr] = av.x; As[lk + 1][lr] = av.y;
        As[lk + 2][lr] = av.z; As[lk + 3][lr] = av.w;
        Bs[lk + 0][lr] = bv.x; Bs[lk + 1][lr] = bv.y;
        Bs[lk + 2][lr] = bv.z; Bs[lk + 3][lr] = bv.w;
        __syncthreads();

#pragma unroll
        for (int kk = 0; kk < 8; kk++) {
            float4 a0 = *(const float4*)(&As[kk][ty * 8]);
            float4 a1 = *(const float4*)(&As[kk][ty * 8 + 4]);
            float4 b0 = *(const float4*)(&Bs[kk][tx * 8]);
            float4 b1 = *(const float4*)(&Bs[kk][tx * 8 + 4]);
            float aa[8] = {a0.x, a0.y, a0.z, a0.w, a1.x, a1.y, a1.z, a1.w};
            float bb[8] = {b0.x, b0.y, b0.z, b0.w, b1.x, b1.y, b1.z, b1.w};
#pragma unroll
            for (int i = 0; i < 8; i++)
#pragma unroll
                for (int j = 0; j < 8; j++)
                    acc[i][j] = fmaf(aa[i], bb[j], acc[i][j]);
        }
    }

#pragma unroll
    for (int i = 0; i < 8; i++) {
        const int row = bm + ty * 8 + i;
        float4* cp = (float4*)(C + (size_t)row * N + bn + tx * 8);
        cp[0] = make_float4(acc[i][0], acc[i][1], acc[i][2], acc[i][3]);
        cp[1] = make_float4(acc[i][4], acc[i][5], acc[i][6], acc[i][7]);
    }
}

// ============================================================================
// RMSNorm + RoPE + scatter. One block per (b*N+n, h), 128 threads (= HD).
// ============================================================================
__global__ void __launch_bounds__(128) norm_rope_scatter(
    const float* __restrict__ qkv, const float* __restrict__ qg,
    const float* __restrict__ kgm, const float* __restrict__ freqs)
{
    const int blk = blockIdx.x;
    const int h = blk & (HN - 1);
    const int m = blk >> 4;              // b*N + n
    const int d = threadIdx.x;
    const int lane = d & 31;
    const int wid = d >> 5;

    const float* base = qkv + (size_t)m * E3;
    float qv = base[h * HDIM + d];
    float kv = base[HN * HDIM + h * HDIM + d];
    float vv = base[2 * HN * HDIM + h * HDIM + d];

    // block reduction of sum(q^2), sum(k^2)
    float sq = qv * qv, sk = kv * kv;
#pragma unroll
    for (int off = 16; off > 0; off >>= 1) {
        sq += __shfl_xor_sync(0xffffffffu, sq, off);
        sk += __shfl_xor_sync(0xffffffffu, sk, off);
    }
    __shared__ float red[8];
    if (lane == 0) { red[wid] = sq; red[4 + wid] = sk; }
    __syncthreads();
    if (d < 2) {
        float s = red[d * 4] + red[d * 4 + 1] + red[d * 4 + 2] + red[d * 4 + 3];
        red[d * 4] = rsqrtf(s * (1.0f / HDIM) + EPSV);
    }
    __syncthreads();
    float qr = qv * red[0] * qg[d] * QSCALE;
    float kr = kv * red[4] * kgm[d];

    // RoPE via lane pair exchange (d and d^1 are in the same warp)
    const int i = d >> 1;
    const float c = freqs[((size_t)m * 64 + i) * 2 + 0];
    const float s = freqs[((size_t)m * 64 + i) * 2 + 1];
    float qo = __shfl_xor_sync(0xffffffffu, qr, 1);
    float ko = __shfl_xor_sync(0xffffffffu, kr, 1);
    float qout, kout;
    if (d & 1) { qout = qo * s + qr * c;  kout = ko * s + kr * c; }
    else       { qout = qr * c - qo * s;  kout = kr * c - ko * s; }

    const int b = m / NN, n = m - b * NN;
    const size_t dst = (((size_t)b * HN + h) * NN + n) * HDIM + d;
    g_q[dst] = qout;
    g_k[dst] = kout;
    g_v[dst] = vv;
}

// ============================================================================
// Flash attention (fp32). One block per (b,h, 64-row q tile). 256 threads.
// KV tiles of 128 keys. Dynamic smem: Qs[128][64] Ks[128][128] Vs[128][128]
// Ps[128][64] = 192 KB.
// ============================================================================
#define SMEM_ATTN ((128 * 64 + 128 * 128 + 128 * 128 + 128 * 64) * 4)

__global__ void __launch_bounds__(256) attn_kernel(
    const float* __restrict__ Q, const float* __restrict__ Kg,
    const float* __restrict__ Vg, float* __restrict__ Out)
{
    extern __shared__ float sm[];
    float* Qs = sm;                        // [d][row]  128 x 64
    float* Ks = Qs + 128 * 64;             // [d][key]  128 x 128
    float* Vs = Ks + 128 * 128;            // [key][d]  128 x 128
    float* Ps = Vs + 128 * 128;            // [key][row] 128 x 64
    __shared__ float sm_m[64], sm_l[64], sm_fac[64];

    const int bid = blockIdx.x;
    const int qt = bid & 31;               // q tile (N/64 = 32)
    const int bh = bid >> 5;               // b*H + h
    const float* Qbase = Q + (size_t)bh * NN * HDIM + (size_t)qt * 64 * HDIM;
    const float* Kbase = Kg + (size_t)bh * NN * HDIM;
    const float* Vbase = Vg + (size_t)bh * NN * HDIM;

    const int tid = threadIdx.x;
    const int kg = tid & 31;               // 4-col group
    const int rg = tid >> 5;               // 8-row group

    // load Q tile, transposed to d-major
    for (int f = tid; f < 64 * 32; f += 256) {
        int row = f >> 5, dq = (f & 31) << 2;
        float4 v = *(const float4*)(Qbase + (size_t)row * HDIM + dq);
        Qs[(dq + 0) * 64 + row] = v.x;
        Qs[(dq + 1) * 64 + row] = v.y;
        Qs[(dq + 2) * 64 + row] = v.z;
        Qs[(dq + 3) * 64 + row] = v.w;
    }
    if (tid < 64) { sm_m[tid] = -1e30f; sm_l[tid] = 0.f; }

    float O[8][4];
#pragma unroll
    for (int i = 0; i < 8; i++)
#pragma unroll
        for (int j = 0; j < 4; j++) O[i][j] = 0.f;
    __syncthreads();

    for (int t = 0; t < NN; t += 128) {
        // load K (transposed) and V (natural)
        for (int f = tid; f < 128 * 32; f += 256) {
            int row = f >> 5, dq = (f & 31) << 2;
            float4 kv = *(const float4*)(Kbase + (size_t)(t + row) * HDIM + dq);
            Ks[(dq + 0) * 128 + row] = kv.x;
            Ks[(dq + 1) * 128 + row] = kv.y;
            Ks[(dq + 2) * 128 + row] = kv.z;
            Ks[(dq + 3) * 128 + row] = kv.w;
            float4 vv = *(const float4*)(Vbase + (size_t)(t + row) * HDIM + dq);
            *(float4*)(Vs + row * 128 + dq) = vv;
        }
        __syncthreads();

        // scores: rows rg*8..+7 x keys kg*4..+3
        float s[8][4];
#pragma unroll
        for (int i = 0; i < 8; i++)
#pragma unroll
            for (int j = 0; j < 4; j++) s[i][j] = 0.f;

        for (int d = 0; d < 128; d++) {
            float4 bq = *(const float4*)(Ks + d * 128 + (kg << 2));
            float4 a0 = *(const float4*)(Qs + d * 64 + (rg << 3));
            float4 a1 = *(const float4*)(Qs + d * 64 + (rg << 3) + 4);
            float aa[8] = {a0.x, a0.y, a0.z, a0.w, a1.x, a1.y, a1.z, a1.w};
            float bb[4] = {bq.x, bq.y, bq.z, bq.w};
#pragma unroll
            for (int i = 0; i < 8; i++)
#pragma unroll
                for (int j = 0; j < 4; j++)
                    s[i][j] = fmaf(aa[i], bb[j], s[i][j]);
        }
#pragma unroll
        for (int j = 0; j < 4; j++)
#pragma unroll
            for (int i = 0; i < 8; i++)
                Ps[((kg << 2) + j) * 64 + (rg << 3) + i] = s[i][j];
        __syncthreads();

        // running max + correction factor
        if (tid < 64) {
            float mo = sm_m[tid];
            float tm = mo;
            for (int j = 0; j < 128; j++) tm = fmaxf(tm, Ps[j * 64 + tid]);
            sm_fac[tid] = __expf(mo - tm);
            sm_m[tid] = tm;
        }
        __syncthreads();

        // exp in place
        for (int e = tid; e < 128 * 64; e += 256) {
            int row = e & 63;
            Ps[e] = __expf(Ps[e] - sm_m[row]);
        }
        // rescale accumulators
        {
            float fac[8];
#pragma unroll
            for (int i = 0; i < 8; i++) fac[i] = sm_fac[(rg << 3) + i];
#pragma unroll
            for (int i = 0; i < 8; i++)
#pragma unroll
                for (int j = 0; j < 4; j++) O[i][j] *= fac[i];
        }
        __syncthreads();

        // running sum (concurrent with PV; both only read Ps)
        if (tid < 64) {
            float ts = 0.f;
            for (int j = 0; j < 128; j++) ts += Ps[j * 64 + tid];
            sm_l[tid] = sm_l[tid] * sm_fac[tid] + ts;
        }

        // PV accumulate
        for (int j = 0; j < 128; j++) {
            float4 vv = *(const float4*)(Vs + j * 128 + (kg << 2));
            float4 p0 = *(const float4*)(Ps + j * 64 + (rg << 3));
            float4 p1 = *(const float4*)(Ps + j * 64 + (rg << 3) + 4);
            float pp[8] = {p0.x, p0.y, p0.z, p0.w, p1.x, p1.y, p1.z, p1.w};
#pragma unroll
            for (int i = 0; i < 8; i++) {
                O[i][0] = fmaf(pp[i], vv.x, O[i][0]);
                O[i][1] = fmaf(pp[i], vv.y, O[i][1]);
                O[i][2] = fmaf(pp[i], vv.z, O[i][2]);
                O[i][3] = fmaf(pp[i], vv.w, O[i][3]);
            }
        }
        __syncthreads();
    }

    // normalize and write: g_ao[b*N+n][h*128 + d]
    const int b = bh >> 4, h = bh & 15;
#pragma unroll
    for (int i = 0; i < 8; i++) {
        int row = (rg << 3) + i;
        int n = qt * 64 + row;
        float inv = 1.0f / sm_l[row];
        float4 o = make_float4(O[i][0] * inv, O[i][1] * inv,
                               O[i][2] * inv, O[i][3] * inv);
        *(float4*)(Out + ((size_t)(b * NN + n)) * (HN * HDIM)
                   + h * HDIM + (kg << 2)) = o;
    }
}

// ============================================================================
// Launch
// ============================================================================
extern "C" void kernel_launch(void* const* d_in, const int* in_sizes, int n_in,
                              void* d_out, int out_size)
{
    const float* x     = (const float*)d_in[0];
    const float* Wqkv  = (const float*)d_in[1];
    const float* qg    = (const float*)d_in[2];
    const float* kg    = (const float*)d_in[3];
    const float* Wout  = (const float*)d_in[4];
    const float* freqs = (const float*)d_in[5];
    float* out = (float*)d_out;

    float *qkv, *q, *k, *v, *ao;
    cudaGetSymbolAddress((void**)&qkv, g_qkv);
    cudaGetSymbolAddress((void**)&q, g_q);
    cudaGetSymbolAddress((void**)&k, g_k);
    cudaGetSymbolAddress((void**)&v, g_v);
    cudaGetSymbolAddress((void**)&ao, g_ao);

    cudaFuncSetAttribute(attn_kernel,
                         cudaFuncAttributeMaxDynamicSharedMemorySize, SMEM_ATTN);

    // 1. QKV GEMM: [4096,2048] x [6144,2048]^T -> [4096,6144]
    {
        dim3 grid(E3 / 128, MROWS / 128);
        sgemm_tn<<<grid, 256>>>(x, Wqkv, qkv, MROWS, E3, DIMM);
    }
    // 2. RMSNorm + RoPE + scatter into [B,H,N,HD]
    {
        norm_rope_scatter<<<MROWS * HN, 128>>>(qkv, qg, kg, freqs);
    }
    // 3. Attention
    {
        attn_kernel<<<BB * HN * (NN / 64), 256, SMEM_ATTN>>>(q, k, v, ao);
    }
    // 4. Output GEMM: [4096,2048] x [2048,2048]^T -> [4096,2048]
    {
        dim3 grid(DIMM / 128, MROWS / 128);
        sgemm_tn<<<grid, 256>>>(ao, Wout, out, MROWS, DIMM, DIMM);
    }
}

// round 3
// speedup vs baseline: 1.6039x; 1.6039x over previous
#include <cuda_runtime.h>
#include <cuda_bf16.h>
#include <cstdint>

// Problem constants
#define DIMM   2048
#define HN     16
#define HDIM   128
#define BB     2
#define NN     2048
#define E3     (3 * HN * HDIM)      // 6144
#define MROWS  (BB * NN)            // 4096
#define EPSV   1e-5f
#define QSCALE 0.08838834764831845f // 1/sqrt(128)

// ---------------- scratch (static device arrays; no allocation) -------------
__device__ float g_qkv[(size_t)MROWS * E3];
__device__ float g_q[(size_t)BB * HN * NN * HDIM];
__device__ float g_k[(size_t)BB * HN * NN * HDIM];
__device__ float g_v[(size_t)BB * HN * NN * HDIM];
__device__ float g_ao[(size_t)MROWS * (HN * HDIM)];

__device__ __nv_bfloat16 g_xhi[(size_t)MROWS * DIMM];
__device__ __nv_bfloat16 g_xlo[(size_t)MROWS * DIMM];
__device__ __nv_bfloat16 g_w1hi[(size_t)E3 * DIMM];
__device__ __nv_bfloat16 g_w1lo[(size_t)E3 * DIMM];
__device__ __nv_bfloat16 g_w2hi[(size_t)DIMM * DIMM];
__device__ __nv_bfloat16 g_w2lo[(size_t)DIMM * DIMM];
__device__ __nv_bfloat16 g_aohi[(size_t)MROWS * DIMM];
__device__ __nv_bfloat16 g_aolo[(size_t)MROWS * DIMM];

// ============================================================================
// helpers
// ============================================================================
__device__ __forceinline__ uint32_t smem_u32(const void* p) {
    uint32_t a;
    asm("{ .reg .u64 t; cvta.to.shared.u64 t, %1; cvt.u32.u64 %0, t; }"
        : "=r"(a) : "l"(p));
    return a;
}
__device__ __forceinline__ void cp_async16(uint32_t dst, const void* src) {
    asm volatile("cp.async.cg.shared.global [%0], [%1], 16;"
                 :: "r"(dst), "l"(src));
}
#define CP_COMMIT() asm volatile("cp.async.commit_group;" ::: "memory")
#define CP_WAIT(n)  asm volatile("cp.async.wait_group %0;" :: "n"(n) : "memory")

__device__ __forceinline__ void ldsm_x4(uint32_t* r, uint32_t addr) {
    asm volatile("ldmatrix.sync.aligned.m8n8.x4.shared.b16 {%0,%1,%2,%3}, [%4];"
                 : "=r"(r[0]), "=r"(r[1]), "=r"(r[2]), "=r"(r[3]) : "r"(addr));
}
__device__ __forceinline__ void mma_bf16(float* c, const uint32_t* a,
                                         const uint32_t* b) {
    asm volatile(
        "mma.sync.aligned.m16n8k16.row.col.f32.bf16.bf16.f32 "
        "{%0,%1,%2,%3}, {%4,%5,%6,%7}, {%8,%9}, {%0,%1,%2,%3};"
        : "+f"(c[0]), "+f"(c[1]), "+f"(c[2]), "+f"(c[3])
        : "r"(a[0]), "r"(a[1]), "r"(a[2]), "r"(a[3]), "r"(b[0]), "r"(b[1]));
}

// ============================================================================
// fp32 -> bf16 hi/lo split
// ============================================================================
__global__ void __launch_bounds__(256) split_bf16(
    const float* __restrict__ in, __nv_bfloat16* __restrict__ hi,
    __nv_bfloat16* __restrict__ lo, int n4)
{
    int i = blockIdx.x * 256 + threadIdx.x;
    if (i >= n4) return;
    float4 v = ((const float4*)in)[i];
    union { __nv_bfloat16 b[4]; uint2 u; } H, L;
    float vv[4] = {v.x, v.y, v.z, v.w};
#pragma unroll
    for (int j = 0; j < 4; j++) {
        __nv_bfloat16 h = __float2bfloat16(vv[j]);
        H.b[j] = h;
        L.b[j] = __float2bfloat16(vv[j] - __bfloat162float(h));
    }
    ((uint2*)hi)[i] = H.u;
    ((uint2*)lo)[i] = L.u;
}

// ============================================================================
// bf16 split GEMM via mma.sync: C[m,n] = sum_k A[m,k]*B[n,k]
// CTA 128x128, BK=32, 256 threads (8 warps, 4x2), warp tile 32x64.
// Smem rows padded to 40 bf16 (80B): 16B-aligned, conflict-free ldmatrix.
// ============================================================================
#define SA 40                         // smem row stride, elements
#define MAT_BYTES (128 * SA * 2)      // 10240 per matrix per stage
#define STAGE_BYTES (4 * MAT_BYTES)   // Ahi Alo Bhi Blo
#define GEMM_SMEM (2 * STAGE_BYTES)   // 81920

__global__ void __launch_bounds__(256, 2) gemm_mma_split(
    const __nv_bfloat16* __restrict__ Ah, const __nv_bfloat16* __restrict__ Al,
    const __nv_bfloat16* __restrict__ Bh, const __nv_bfloat16* __restrict__ Bl,
    float* __restrict__ C, int Ntot, int K)
{
    extern __shared__ __align__(128) char sm[];
    const uint32_t sbase = smem_u32(sm);
    const int tid = threadIdx.x;
    const int lane = tid & 31;
    const int wid = tid >> 5;
    const int warp_m = wid & 3;        // 4 warps over M: 32 rows each
    const int warp_n = wid >> 2;       // 2 warps over N: 64 cols each
    const int bm = blockIdx.y * 128;
    const int bn = blockIdx.x * 128;

    const __nv_bfloat16* srcs[4] = {Ah, Al, Bh, Bl};
    const int rowbase[4] = {bm, bm, bn, bn};

    // cp.async mapping: 2048 16B-chunks per stage, 8 per thread
    // chunk idx -> matrix (idx>>9), row ((idx>>2)&127), c (idx&3)
    auto issue_stage = [&](int stage, int kc) {
        uint32_t sdst = sbase + stage * STAGE_BYTES;
#pragma unroll
        for (int t = 0; t < 8; t++) {
            int idx = tid + t * 256;
            int mat = idx >> 9;
            int row = (idx >> 2) & 127;
            int c = idx & 3;
            uint32_t dst = sdst + mat * MAT_BYTES + (row * SA + c * 8) * 2;
            const __nv_bfloat16* src =
                srcs[mat] + (size_t)(rowbase[mat] + row) * K + kc + c * 8;
            cp_async16(dst, src);
        }
        CP_COMMIT();
    };

    float acc[2][8][4];
#pragma unroll
    for (int a = 0; a < 2; a++)
#pragma unroll
        for (int b = 0; b < 8; b++)
#pragma unroll
            for (int c = 0; c < 4; c++) acc[a][b][c] = 0.f;

    const int nk = K / 32;
    issue_stage(0, 0);

    // ldmatrix address components (element offsets; *2 for bytes)
    // A: rows = warp_m*32 + tm*16 + (lane&15), chunk8 = ks*2 + (lane>>4)
    const int a_r = warp_m * 32 + (lane & 15);
    const int a_c8 = lane >> 4;
    // B: rows = warp_n*64 + g*16 + (lane&7) + (lane>>4)*8, chunk8 = ks*2 + ((lane>>3)&1)
    const int b_r = warp_n * 64 + (lane & 7) + (lane >> 4) * 8;
    const int b_c8 = (lane >> 3) & 1;

    for (int kb = 0; kb < nk; kb++) {
        if (kb < nk - 1) {
            issue_stage((kb + 1) & 1, (kb + 1) * 32);
            CP_WAIT(1);
        } else {
            CP_WAIT(0);
        }
        __syncthreads();

        const uint32_t st = sbase + (kb & 1) * STAGE_BYTES;
        const uint32_t sAh = st;
        const uint32_t sAl = st + MAT_BYTES;
        const uint32_t sBh = st + 2 * MAT_BYTES;
        const uint32_t sBl = st + 3 * MAT_BYTES;

#pragma unroll
        for (int ks = 0; ks < 2; ks++) {
            uint32_t ahi[2][4], alo[2][4];
#pragma unroll
            for (int tm = 0; tm < 2; tm++) {
                uint32_t off = ((a_r + tm * 16) * SA + (ks * 2 + a_c8) * 8) * 2;
                ldsm_x4(ahi[tm], sAh + off);
                ldsm_x4(alo[tm], sAl + off);
            }
#pragma unroll
            for (int g = 0; g < 4; g++) {
                uint32_t bhi[4], blo[4];
                uint32_t off = ((b_r + g * 16) * SA + (ks * 2 + b_c8) * 8) * 2;
                ldsm_x4(bhi, sBh + off);
                ldsm_x4(blo, sBl + off);
#pragma unroll
                for (int tm = 0; tm < 2; tm++) {
#pragma unroll
                    for (int sub = 0; sub < 2; sub++) {
                        float* cc = acc[tm][g * 2 + sub];
                        mma_bf16(cc, ahi[tm], bhi + sub * 2);
                        mma_bf16(cc, ahi[tm], blo + sub * 2);
                        mma_bf16(cc, alo[tm], bhi + sub * 2);
                    }
                }
            }
        }
        __syncthreads();
    }

    // epilogue
    const int crow = lane >> 2;
    const int ccol = (lane & 3) * 2;
#pragma unroll
    for (int tm = 0; tm < 2; tm++) {
#pragma unroll
        for (int t = 0; t < 8; t++) {
            int row = bm + warp_m * 32 + tm * 16 + crow;
            int col = bn + warp_n * 64 + t * 8 + ccol;
            float* p0 = C + (size_t)row * Ntot + col;
            float* p1 = C + (size_t)(row + 8) * Ntot + col;
            p0[0] = acc[tm][t][0]; p0[1] = acc[tm][t][1];
            p1[0] = acc[tm][t][2]; p1[1] = acc[tm][t][3];
        }
    }
}

// ============================================================================
// RMSNorm + RoPE + scatter. One block per (b*N+n, h), 128 threads.
// ============================================================================
__global__ void __launch_bounds__(128) norm_rope_scatter(
    const float* __restrict__ qkv, const float* __restrict__ qg,
    const float* __restrict__ kgm, const float* __restrict__ freqs)
{
    const int blk = blockIdx.x;
    const int h = blk & (HN - 1);
    const int m = blk >> 4;
    const int d = threadIdx.x;
    const int lane = d & 31;
    const int wid = d >> 5;

    const float* base = qkv + (size_t)m * E3;
    float qv = base[h * HDIM + d];
    float kv = base[HN * HDIM + h * HDIM + d];
    float vv = base[2 * HN * HDIM + h * HDIM + d];

    float sq = qv * qv, sk = kv * kv;
#pragma unroll
    for (int off = 16; off > 0; off >>= 1) {
        sq += __shfl_xor_sync(0xffffffffu, sq, off);
        sk += __shfl_xor_sync(0xffffffffu, sk, off);
    }
    __shared__ float red[8];
    if (lane == 0) { red[wid] = sq; red[4 + wid] = sk; }
    __syncthreads();
    if (d < 2) {
        float s = red[d * 4] + red[d * 4 + 1] + red[d * 4 + 2] + red[d * 4 + 3];
        red[d * 4] = rsqrtf(s * (1.0f / HDIM) + EPSV);
    }
    __syncthreads();
    float qr = qv * red[0] * qg[d] * QSCALE;
    float kr = kv * red[4] * kgm[d];

    const int i = d >> 1;
    const float c = freqs[((size_t)m * 64 + i) * 2 + 0];
    const float s = freqs[((size_t)m * 64 + i) * 2 + 1];
    float qo = __shfl_xor_sync(0xffffffffu, qr, 1);
    float ko = __shfl_xor_sync(0xffffffffu, kr, 1);
    float qout, kout;
    if (d & 1) { qout = qo * s + qr * c;  kout = ko * s + kr * c; }
    else       { qout = qr * c - qo * s;  kout = kr * c - ko * s; }

    const int b = m / NN, n = m - b * NN;
    const size_t dst = (((size_t)b * HN + h) * NN + n) * HDIM + d;
    g_q[dst] = qout;
    g_k[dst] = kout;
    g_v[dst] = vv;
}

// ============================================================================
// Flash attention (fp32 SIMT). One block per (b,h, 64-row q tile). 256 thr.
// ============================================================================
#define SMEM_ATTN ((128 * 64 + 128 * 128 + 128 * 128 + 128 * 64) * 4)

__global__ void __launch_bounds__(256) attn_kernel(
    const float* __restrict__ Q, const float* __restrict__ Kg,
    const float* __restrict__ Vg, float* __restrict__ Out)
{
    extern __shared__ float smf[];
    float* Qs = smf;
    float* Ks = Qs + 128 * 64;
    float* Vs = Ks + 128 * 128;
    float* Ps = Vs + 128 * 128;
    __shared__ float sm_m[64], sm_l[64], sm_fac[64];

    const int bid = blockIdx.x;
    const int qt = bid & 31;
    const int bh = bid >> 5;
    const float* Qbase = Q + (size_t)bh * NN * HDIM + (size_t)qt * 64 * HDIM;
    const float* Kbase = Kg + (size_t)bh * NN * HDIM;
    const float* Vbase = Vg + (size_t)bh * NN * HDIM;

    const int tid = threadIdx.x;
    const int kg = tid & 31;
    const int rg = tid >> 5;

    for (int f = tid; f < 64 * 32; f += 256) {
        int row = f >> 5, dq = (f & 31) << 2;
        float4 v = *(const float4*)(Qbase + (size_t)row * HDIM + dq);
        Qs[(dq + 0) * 64 + row] = v.x;
        Qs[(dq + 1) * 64 + row] = v.y;
        Qs[(dq + 2) * 64 + row] = v.z;
        Qs[(dq + 3) * 64 + row] = v.w;
    }
    if (tid < 64) { sm_m[tid] = -1e30f; sm_l[tid] = 0.f; }

    float O[8][4];
#pragma unroll
    for (int i = 0; i < 8; i++)
#pragma unroll
        for (int j = 0; j < 4; j++) O[i][j] = 0.f;
    __syncthreads();

    for (int t = 0; t < NN; t += 128) {
        for (int f = tid; f < 128 * 32; f += 256) {
            int row = f >> 5, dq = (f & 31) << 2;
            float4 kv = *(const float4*)(Kbase + (size_t)(t + row) * HDIM + dq);
            Ks[(dq + 0) * 128 + row] = kv.x;
            Ks[(dq + 1) * 128 + row] = kv.y;
            Ks[(dq + 2) * 128 + row] = kv.z;
            Ks[(dq + 3) * 128 + row] = kv.w;
            float4 vv = *(const float4*)(Vbase + (size_t)(t + row) * HDIM + dq);
            *(float4*)(Vs + row * 128 + dq) = vv;
        }
        __syncthreads();

        float s[8][4];
#pragma unroll
        for (int i = 0; i < 8; i++)
#pragma unroll
            for (int j = 0; j < 4; j++) s[i][j] = 0.f;

        for (int d = 0; d < 128; d++) {
            float4 bq = *(const float4*)(Ks + d * 128 + (kg << 2));
            float4 a0 = *(const float4*)(Qs + d * 64 + (rg << 3));
            float4 a1 = *(const float4*)(Qs + d * 64 + (rg << 3) + 4);
            float aa[8] = {a0.x, a0.y, a0.z, a0.w, a1.x, a1.y, a1.z, a1.w};
            float bb[4] = {bq.x, bq.y, bq.z, bq.w};
#pragma unroll
            for (int i = 0; i < 8; i++)
#pragma unroll
                for (int j = 0; j < 4; j++)
                    s[i][j] = fmaf(aa[i], bb[j], s[i][j]);
        }
#pragma unroll
        for (int j = 0; j < 4; j++)
#pragma unroll
            for (int i = 0; i < 8; i++)
                Ps[((kg << 2) + j) * 64 + (rg << 3) + i] = s[i][j];
        __syncthreads();

        if (tid < 64) {
            float mo = sm_m[tid];
            float tm = mo;
            for (int j = 0; j < 128; j++) tm = fmaxf(tm, Ps[j * 64 + tid]);
            sm_fac[tid] = __expf(mo - tm);
            sm_m[tid] = tm;
        }
        __syncthreads();

        for (int e = tid; e < 128 * 64; e += 256) {
            int row = e & 63;
            Ps[e] = __expf(Ps[e] - sm_m[row]);
        }
        {
            float fac[8];
#pragma unroll
            for (int i = 0; i < 8; i++) fac[i] = sm_fac[(rg << 3) + i];
#pragma unroll
            for (int i = 0; i < 8; i++)
#pragma unroll
                for (int j = 0; j < 4; j++) O[i][j] *= fac[i];
        }
        __syncthreads();

        if (tid < 64) {
            float ts = 0.f;
            for (int j = 0; j < 128; j++) ts += Ps[j * 64 + tid];
            sm_l[tid] = sm_l[tid] * sm_fac[tid] + ts;
        }

        for (int j = 0; j < 128; j++) {
            float4 vv = *(const float4*)(Vs + j * 128 + (kg << 2));
            float4 p0 = *(const float4*)(Ps + j * 64 + (rg << 3));
            float4 p1 = *(const float4*)(Ps + j * 64 + (rg << 3) + 4);
            float pp[8] = {p0.x, p0.y, p0.z, p0.w, p1.x, p1.y, p1.z, p1.w};
#pragma unroll
            for (int i = 0; i < 8; i++) {
                O[i][0] = fmaf(pp[i], vv.x, O[i][0]);
                O[i][1] = fmaf(pp[i], vv.y, O[i][1]);
                O[i][2] = fmaf(pp[i], vv.z, O[i][2]);
                O[i][3] = fmaf(pp[i], vv.w, O[i][3]);
            }
        }
        __syncthreads();
    }

    const int b = bh >> 4, h = bh & 15;
#pragma unroll
    for (int i = 0; i < 8; i++) {
        int row = (rg << 3) + i;
        int n = qt * 64 + row;
        float inv = 1.0f / sm_l[row];
        float4 o = make_float4(O[i][0] * inv, O[i][1] * inv,
                               O[i][2] * inv, O[i][3] * inv);
        *(float4*)(Out + ((size_t)(b * NN + n)) * (HN * HDIM)
                   + h * HDIM + (kg << 2)) = o;
    }
}

// ============================================================================
// Launch
// ============================================================================
extern "C" void kernel_launch(void* const* d_in, const int* in_sizes, int n_in,
                              void* d_out, int out_size)
{
    const float* x     = (const float*)d_in[0];
    const float* Wqkv  = (const float*)d_in[1];
    const float* qg    = (const float*)d_in[2];
    const float* kg    = (const float*)d_in[3];
    const float* Wout  = (const float*)d_in[4];
    const float* freqs = (const float*)d_in[5];
    float* out = (float*)d_out;

    float *qkv, *q, *k, *v, *ao;
    __nv_bfloat16 *xhi, *xlo, *w1hi, *w1lo, *w2hi, *w2lo, *aohi, *aolo;
    cudaGetSymbolAddress((void**)&qkv, g_qkv);
    cudaGetSymbolAddress((void**)&q, g_q);
    cudaGetSymbolAddress((void**)&k, g_k);
    cudaGetSymbolAddress((void**)&v, g_v);
    cudaGetSymbolAddress((void**)&ao, g_ao);
    cudaGetSymbolAddress((void**)&xhi, g_xhi);
    cudaGetSymbolAddress((void**)&xlo, g_xlo);
    cudaGetSymbolAddress((void**)&w1hi, g_w1hi);
    cudaGetSymbolAddress((void**)&w1lo, g_w1lo);
    cudaGetSymbolAddress((void**)&w2hi, g_w2hi);
    cudaGetSymbolAddress((void**)&w2lo, g_w2lo);
    cudaGetSymbolAddress((void**)&aohi, g_aohi);
    cudaGetSymbolAddress((void**)&aolo, g_aolo);

    cudaFuncSetAttribute(attn_kernel,
                         cudaFuncAttributeMaxDynamicSharedMemorySize, SMEM_ATTN);
    cudaFuncSetAttribute(gemm_mma_split,
                         cudaFuncAttributeMaxDynamicSharedMemorySize, GEMM_SMEM);

    // splits
    {
        int n4x = (MROWS * DIMM) / 4;
        split_bf16<<<n4x / 256, 256>>>(x, xhi, xlo, n4x);
        int n4w1 = (E3 * DIMM) / 4;
        split_bf16<<<n4w1 / 256, 256>>>(Wqkv, w1hi, w1lo, n4w1);
        int n4w2 = (DIMM * DIMM) / 4;
        split_bf16<<<n4w2 / 256, 256>>>(Wout, w2hi, w2lo, n4w2);
    }
    // 1. QKV GEMM
    {
        dim3 grid(E3 / 128, MROWS / 128);
        gemm_mma_split<<<grid, 256, GEMM_SMEM>>>(xhi, xlo, w1hi, w1lo, qkv, E3, DIMM);
    }
    // 2. RMSNorm + RoPE + scatter
    norm_rope_scatter<<<MROWS * HN, 128>>>(qkv, qg, kg, freqs);
    // 3. Attention
    attn_kernel<<<BB * HN * (NN / 64), 256, SMEM_ATTN>>>(q, k, v, ao);
    // 4. split attention output, out GEMM
    {
        int n4a = (MROWS * DIMM) / 4;
        split_bf16<<<n4a / 256, 256>>>(ao, aohi, aolo, n4a);
        dim3 grid(DIMM / 128, MROWS / 128);
        gemm_mma_split<<<grid, 256, GEMM_SMEM>>>(aohi, aolo, w2hi, w2lo, out, DIMM, DIMM);
    }
}

// round 4
// speedup vs baseline: 3.5176x; 2.1931x over previous
#include <cuda_runtime.h>
#include <cuda_bf16.h>
#include <cstdint>

// Problem constants
#define DIMM   2048
#define HN     16
#define HDIM   128
#define BB     2
#define NN     2048
#define E3     (3 * HN * HDIM)      // 6144
#define MROWS  (BB * NN)            // 4096
#define EPSV   1e-5f
#define QSCALE 0.08838834764831845f // 1/sqrt(128)

// ---------------- scratch (static device arrays; no allocation) -------------
__device__ float g_qkv[(size_t)MROWS * E3];

__device__ __nv_bfloat16 g_qhi[(size_t)BB * HN * NN * HDIM];
__device__ __nv_bfloat16 g_qlo[(size_t)BB * HN * NN * HDIM];
__device__ __nv_bfloat16 g_khi[(size_t)BB * HN * NN * HDIM];
__device__ __nv_bfloat16 g_klo[(size_t)BB * HN * NN * HDIM];
__device__ __nv_bfloat16 g_vhi[(size_t)BB * HN * NN * HDIM];
__device__ __nv_bfloat16 g_vlo[(size_t)BB * HN * NN * HDIM];

__device__ __nv_bfloat16 g_xhi[(size_t)MROWS * DIMM];
__device__ __nv_bfloat16 g_xlo[(size_t)MROWS * DIMM];
__device__ __nv_bfloat16 g_w1hi[(size_t)E3 * DIMM];
__device__ __nv_bfloat16 g_w1lo[(size_t)E3 * DIMM];
__device__ __nv_bfloat16 g_w2hi[(size_t)DIMM * DIMM];
__device__ __nv_bfloat16 g_w2lo[(size_t)DIMM * DIMM];
__device__ __nv_bfloat16 g_aohi[(size_t)MROWS * DIMM];
__device__ __nv_bfloat16 g_aolo[(size_t)MROWS * DIMM];

// ============================================================================
// helpers
// ============================================================================
__device__ __forceinline__ uint32_t smem_u32(const void* p) {
    uint32_t a;
    asm("{ .reg .u64 t; cvta.to.shared.u64 t, %1; cvt.u32.u64 %0, t; }"
        : "=r"(a) : "l"(p));
    return a;
}
__device__ __forceinline__ void cp_async16(uint32_t dst, const void* src) {
    asm volatile("cp.async.cg.shared.global [%0], [%1], 16;"
                 :: "r"(dst), "l"(src));
}
#define CP_COMMIT() asm volatile("cp.async.commit_group;" ::: "memory")
#define CP_WAIT(n)  asm volatile("cp.async.wait_group %0;" :: "n"(n) : "memory")

__device__ __forceinline__ void ldsm_x4(uint32_t* r, uint32_t addr) {
    asm volatile("ldmatrix.sync.aligned.m8n8.x4.shared.b16 {%0,%1,%2,%3}, [%4];"
                 : "=r"(r[0]), "=r"(r[1]), "=r"(r[2]), "=r"(r[3]) : "r"(addr));
}
__device__ __forceinline__ void ldsm_x4_t(uint32_t* r, uint32_t addr) {
    asm volatile("ldmatrix.sync.aligned.m8n8.x4.trans.shared.b16 {%0,%1,%2,%3}, [%4];"
                 : "=r"(r[0]), "=r"(r[1]), "=r"(r[2]), "=r"(r[3]) : "r"(addr));
}
__device__ __forceinline__ void mma_bf16(float* c, const uint32_t* a,
                                         const uint32_t* b) {
    asm volatile(
        "mma.sync.aligned.m16n8k16.row.col.f32.bf16.bf16.f32 "
        "{%0,%1,%2,%3}, {%4,%5,%6,%7}, {%8,%9}, {%0,%1,%2,%3};"
        : "+f"(c[0]), "+f"(c[1]), "+f"(c[2]), "+f"(c[3])
        : "r"(a[0]), "r"(a[1]), "r"(a[2]), "r"(a[3]), "r"(b[0]), "r"(b[1]));
}
// split two floats into packed bf16x2 hi and lo words
__device__ __forceinline__ void split2(float x, float y, uint32_t& hi, uint32_t& lo) {
    __nv_bfloat16 hx = __float2bfloat16(x), hy = __float2bfloat16(y);
    float rx = x - __bfloat162float(hx), ry = y - __bfloat162float(hy);
    __nv_bfloat162 H; H.x = hx; H.y = hy;
    __nv_bfloat162 L; L.x = __float2bfloat16(rx); L.y = __float2bfloat16(ry);
    hi = *(uint32_t*)&H;
    lo = *(uint32_t*)&L;
}

// ============================================================================
// fp32 -> bf16 hi/lo split
// ============================================================================
__global__ void __launch_bounds__(256) split_bf16(
    const float* __restrict__ in, __nv_bfloat16* __restrict__ hi,
    __nv_bfloat16* __restrict__ lo, int n4)
{
    int i = blockIdx.x * 256 + threadIdx.x;
    if (i >= n4) return;
    float4 v = ((const float4*)in)[i];
    union { __nv_bfloat16 b[4]; uint2 u; } H, L;
    float vv[4] = {v.x, v.y, v.z, v.w};
#pragma unroll
    for (int j = 0; j < 4; j++) {
        __nv_bfloat16 h = __float2bfloat16(vv[j]);
        H.b[j] = h;
        L.b[j] = __float2bfloat16(vv[j] - __bfloat162float(h));
    }
    ((uint2*)hi)[i] = H.u;
    ((uint2*)lo)[i] = L.u;
}

// ============================================================================
// bf16 split GEMM via mma.sync (unchanged from R3, passing)
// ============================================================================
#define SA 40
#define MAT_BYTES (128 * SA * 2)
#define STAGE_BYTES (4 * MAT_BYTES)
#define GEMM_SMEM (2 * STAGE_BYTES)

__global__ void __launch_bounds__(256, 2) gemm_mma_split(
    const __nv_bfloat16* __restrict__ Ah, const __nv_bfloat16* __restrict__ Al,
    const __nv_bfloat16* __restrict__ Bh, const __nv_bfloat16* __restrict__ Bl,
    float* __restrict__ C, int Ntot, int K)
{
    extern __shared__ __align__(128) char sm[];
    const uint32_t sbase = smem_u32(sm);
    const int tid = threadIdx.x;
    const int lane = tid & 31;
    const int wid = tid >> 5;
    const int warp_m = wid & 3;
    const int warp_n = wid >> 2;
    const int bm = blockIdx.y * 128;
    const int bn = blockIdx.x * 128;

    const __nv_bfloat16* srcs[4] = {Ah, Al, Bh, Bl};
    const int rowbase[4] = {bm, bm, bn, bn};

    auto issue_stage = [&](int stage, int kc) {
        uint32_t sdst = sbase + stage * STAGE_BYTES;
#pragma unroll
        for (int t = 0; t < 8; t++) {
            int idx = tid + t * 256;
            int mat = idx >> 9;
            int row = (idx >> 2) & 127;
            int c = idx & 3;
            uint32_t dst = sdst + mat * MAT_BYTES + (row * SA + c * 8) * 2;
            const __nv_bfloat16* src =
                srcs[mat] + (size_t)(rowbase[mat] + row) * K + kc + c * 8;
            cp_async16(dst, src);
        }
        CP_COMMIT();
    };

    float acc[2][8][4];
#pragma unroll
    for (int a = 0; a < 2; a++)
#pragma unroll
        for (int b = 0; b < 8; b++)
#pragma unroll
            for (int c = 0; c < 4; c++) acc[a][b][c] = 0.f;

    const int nk = K / 32;
    issue_stage(0, 0);

    const int a_r = warp_m * 32 + (lane & 15);
    const int a_c8 = lane >> 4;
    const int b_r = warp_n * 64 + (lane & 7) + (lane >> 4) * 8;
    const int b_c8 = (lane >> 3) & 1;

    for (int kb = 0; kb < nk; kb++) {
        if (kb < nk - 1) {
            issue_stage((kb + 1) & 1, (kb + 1) * 32);
            CP_WAIT(1);
        } else {
            CP_WAIT(0);
        }
        __syncthreads();

        const uint32_t st = sbase + (kb & 1) * STAGE_BYTES;
        const uint32_t sAh = st;
        const uint32_t sAl = st + MAT_BYTES;
        const uint32_t sBh = st + 2 * MAT_BYTES;
        const uint32_t sBl = st + 3 * MAT_BYTES;

#pragma unroll
        for (int ks = 0; ks < 2; ks++) {
            uint32_t ahi[2][4], alo[2][4];
#pragma unroll
            for (int tm = 0; tm < 2; tm++) {
                uint32_t off = ((a_r + tm * 16) * SA + (ks * 2 + a_c8) * 8) * 2;
                ldsm_x4(ahi[tm], sAh + off);
                ldsm_x4(alo[tm], sAl + off);
            }
#pragma unroll
            for (int g = 0; g < 4; g++) {
                uint32_t bhi[4], blo[4];
                uint32_t off = ((b_r + g * 16) * SA + (ks * 2 + b_c8) * 8) * 2;
                ldsm_x4(bhi, sBh + off);
                ldsm_x4(blo, sBl + off);
#pragma unroll
                for (int tm = 0; tm < 2; tm++) {
#pragma unroll
                    for (int sub = 0; sub < 2; sub++) {
                        float* cc = acc[tm][g * 2 + sub];
                        mma_bf16(cc, ahi[tm], bhi + sub * 2);
                        mma_bf16(cc, ahi[tm], blo + sub * 2);
                        mma_bf16(cc, alo[tm], bhi + sub * 2);
                    }
                }
            }
        }
        __syncthreads();
    }

    const int crow = lane >> 2;
    const int ccol = (lane & 3) * 2;
#pragma unroll
    for (int tm = 0; tm < 2; tm++) {
#pragma unroll
        for (int t = 0; t < 8; t++) {
            int row = bm + warp_m * 32 + tm * 16 + crow;
            int col = bn + warp_n * 64 + t * 8 + ccol;
            float* p0 = C + (size_t)row * Ntot + col;
            float* p1 = C + (size_t)(row + 8) * Ntot + col;
            p0[0] = acc[tm][t][0]; p0[1] = acc[tm][t][1];
            p1[0] = acc[tm][t][2]; p1[1] = acc[tm][t][3];
        }
    }
}

// ============================================================================
// RMSNorm + RoPE + scatter -> bf16 hi/lo q,k,v
// ============================================================================
__global__ void __launch_bounds__(128) norm_rope_scatter(
    const float* __restrict__ qkv, const float* __restrict__ qg,
    const float* __restrict__ kgm, const float* __restrict__ freqs)
{
    const int blk = blockIdx.x;
    const int h = blk & (HN - 1);
    const int m = blk >> 4;
    const int d = threadIdx.x;
    const int lane = d & 31;
    const int wid = d >> 5;

    const float* base = qkv + (size_t)m * E3;
    float qv = base[h * HDIM + d];
    float kv = base[HN * HDIM + h * HDIM + d];
    float vv = base[2 * HN * HDIM + h * HDIM + d];

    float sq = qv * qv, sk = kv * kv;
#pragma unroll
    for (int off = 16; off > 0; off >>= 1) {
        sq += __shfl_xor_sync(0xffffffffu, sq, off);
        sk += __shfl_xor_sync(0xffffffffu, sk, off);
    }
    __shared__ float red[8];
    if (lane == 0) { red[wid] = sq; red[4 + wid] = sk; }
    __syncthreads();
    if (d < 2) {
        float s = red[d * 4] + red[d * 4 + 1] + red[d * 4 + 2] + red[d * 4 + 3];
        red[d * 4] = rsqrtf(s * (1.0f / HDIM) + EPSV);
    }
    __syncthreads();
    float qr = qv * red[0] * qg[d] * QSCALE;
    float kr = kv * red[4] * kgm[d];

    const int i = d >> 1;
    const float c = freqs[((size_t)m * 64 + i) * 2 + 0];
    const float s = freqs[((size_t)m * 64 + i) * 2 + 1];
    float qo = __shfl_xor_sync(0xffffffffu, qr, 1);
    float ko = __shfl_xor_sync(0xffffffffu, kr, 1);
    float qout, kout;
    if (d & 1) { qout = qo * s + qr * c;  kout = ko * s + kr * c; }
    else       { qout = qr * c - qo * s;  kout = kr * c - ko * s; }

    const int b = m / NN, n = m - b * NN;
    const size_t dst = (((size_t)b * HN + h) * NN + n) * HDIM + d;
    __nv_bfloat16 qh = __float2bfloat16(qout);
    __nv_bfloat16 kh = __float2bfloat16(kout);
    __nv_bfloat16 vh = __float2bfloat16(vv);
    g_qhi[dst] = qh; g_qlo[dst] = __float2bfloat16(qout - __bfloat162float(qh));
    g_khi[dst] = kh; g_klo[dst] = __float2bfloat16(kout - __bfloat162float(kh));
    g_vhi[dst] = vh; g_vlo[dst] = __float2bfloat16(vv - __bfloat162float(vh));
}

// ============================================================================
// Flash attention, bf16-split mma.sync.
// CTA: 128 q-rows x all keys. 8 warps x 16 rows. Key tiles of 128.
// smem: Qhi Qlo Khi Klo Vhi Vlo, 128x128 bf16 each, row stride 136.
// ============================================================================
#define SK 136
#define ATT_MAT (128 * SK * 2)         // 34816
#define ATT_SMEM (6 * ATT_MAT)         // 208896

__global__ void __launch_bounds__(256, 1) attn_mma(
    const __nv_bfloat16* __restrict__ Qh, const __nv_bfloat16* __restrict__ Ql,
    const __nv_bfloat16* __restrict__ Kh, const __nv_bfloat16* __restrict__ Kl,
    const __nv_bfloat16* __restrict__ Vh, const __nv_bfloat16* __restrict__ Vl,
    __nv_bfloat16* __restrict__ Ohi, __nv_bfloat16* __restrict__ Olo)
{
    extern __shared__ __align__(128) char smA[];
    const uint32_t sbase = smem_u32(smA);
    const uint32_t sQh = sbase, sQl = sbase + ATT_MAT;
    const uint32_t sKh = sbase + 2 * ATT_MAT, sKl = sbase + 3 * ATT_MAT;
    const uint32_t sVh = sbase + 4 * ATT_MAT, sVl = sbase + 5 * ATT_MAT;

    const int tid = threadIdx.x;
    const int lane = tid & 31;
    const int wid = tid >> 5;
    const int qt = blockIdx.x & 15;
    const int bh = blockIdx.x >> 4;

    const size_t seqbase = (size_t)bh * NN * HDIM;
    const __nv_bfloat16* qh_p = Qh + seqbase + (size_t)qt * 128 * HDIM;
    const __nv_bfloat16* ql_p = Ql + seqbase + (size_t)qt * 128 * HDIM;

    // load Q hi/lo (row-major 128x128, stride SK)
    {
        // 2048 16B-chunks per matrix; 8 per thread
#pragma unroll
        for (int t = 0; t < 8; t++) {
            int idx = tid + t * 256;
            int row = idx >> 4, c8 = idx & 15;
            uint32_t off = (row * SK + c8 * 8) * 2;
            cp_async16(sQh + off, qh_p + row * HDIM + c8 * 8);
            cp_async16(sQl + off, ql_p + row * HDIM + c8 * 8);
        }
        CP_COMMIT();
    }

    float o[16][4];
#pragma unroll
    for (int t = 0; t < 16; t++)
#pragma unroll
        for (int j = 0; j < 4; j++) o[t][j] = 0.f;
    float mrow0 = -1e30f, mrow1 = -1e30f, lrow0 = 0.f, lrow1 = 0.f;

    const int a_r = wid * 16 + (lane & 15);
    const int a_c8 = lane >> 4;
    const int kb_r = (lane & 7) + (lane >> 4) * 8;   // + nt*16
    const int kb_c8 = (lane >> 3) & 1;
    const int v_r = lane & 15;                        // + kk*16
    const int v_c8 = lane >> 4;                       // *8 + nt*16

    for (int t0 = 0; t0 < NN; t0 += 128) {
        // load K,V hi/lo tiles
        const __nv_bfloat16* kh_p = Kh + seqbase + (size_t)t0 * HDIM;
        const __nv_bfloat16* kl_p = Kl + seqbase + (size_t)t0 * HDIM;
        const __nv_bfloat16* vh_p = Vh + seqbase + (size_t)t0 * HDIM;
        const __nv_bfloat16* vl_p = Vl + seqbase + (size_t)t0 * HDIM;
#pragma unroll
        for (int t = 0; t < 8; t++) {
            int idx = tid + t * 256;
            int row = idx >> 4, c8 = idx & 15;
            uint32_t off = (row * SK + c8 * 8) * 2;
            int go = row * HDIM + c8 * 8;
            cp_async16(sKh + off, kh_p + go);
            cp_async16(sKl + off, kl_p + go);
            cp_async16(sVh + off, vh_p + go);
            cp_async16(sVl + off, vl_p + go);
        }
        CP_COMMIT();
        CP_WAIT(0);
        __syncthreads();

        // ---- S = Q K^T (3 split passes) ----
        float s[16][4];
#pragma unroll
        for (int t = 0; t < 16; t++)
#pragma unroll
            for (int j = 0; j < 4; j++) s[t][j] = 0.f;

#pragma unroll
        for (int kk = 0; kk < 8; kk++) {
            uint32_t qa[4], qb[4];
            uint32_t aoff = (a_r * SK + kk * 16 + a_c8 * 8) * 2;
            ldsm_x4(qa, sQh + aoff);
            ldsm_x4(qb, sQl + aoff);
#pragma unroll
            for (int nt = 0; nt < 8; nt++) {
                uint32_t kf[4], kg2[4];
                uint32_t boff = ((nt * 16 + kb_r) * SK + kk * 16 + kb_c8 * 8) * 2;
                ldsm_x4(kf, sKh + boff);
                ldsm_x4(kg2, sKl + boff);
                mma_bf16(s[2 * nt], qa, kf);
                mma_bf16(s[2 * nt], qa, kg2);
                mma_bf16(s[2 * nt], qb, kf);
                mma_bf16(s[2 * nt + 1], qa, kf + 2);
                mma_bf16(s[2 * nt + 1], qa, kg2 + 2);
                mma_bf16(s[2 * nt + 1], qb, kf + 2);
            }
        }

        // ---- online softmax (quad-local) ----
        float tm0 = -1e30f, tm1 = -1e30f;
#pragma unroll
        for (int t = 0; t < 16; t++) {
            tm0 = fmaxf(tm0, fmaxf(s[t][0], s[t][1]));
            tm1 = fmaxf(tm1, fmaxf(s[t][2], s[t][3]));
        }
        tm0 = fmaxf(tm0, __shfl_xor_sync(0xffffffffu, tm0, 1));
        tm0 = fmaxf(tm0, __shfl_xor_sync(0xffffffffu, tm0, 2));
        tm1 = fmaxf(tm1, __shfl_xor_sync(0xffffffffu, tm1, 1));
        tm1 = fmaxf(tm1, __shfl_xor_sync(0xffffffffu, tm1, 2));
        float mn0 = fmaxf(mrow0, tm0), mn1 = fmaxf(mrow1, tm1);
        float fac0 = __expf(mrow0 - mn0), fac1 = __expf(mrow1 - mn1);
        mrow0 = mn0; mrow1 = mn1;

        float ts0 = 0.f, ts1 = 0.f;
#pragma unroll
        for (int t = 0; t < 16; t++) {
            s[t][0] = __expf(s[t][0] - mn0);
            s[t][1] = __expf(s[t][1] - mn0);
            s[t][2] = __expf(s[t][2] - mn1);
            s[t][3] = __expf(s[t][3] - mn1);
            ts0 += s[t][0] + s[t][1];
            ts1 += s[t][2] + s[t][3];
        }
        ts0 += __shfl_xor_sync(0xffffffffu, ts0, 1);
        ts0 += __shfl_xor_sync(0xffffffffu, ts0, 2);
        ts1 += __shfl_xor_sync(0xffffffffu, ts1, 1);
        ts1 += __shfl_xor_sync(0xffffffffu, ts1, 2);
        lrow0 = lrow0 * fac0 + ts0;
        lrow1 = lrow1 * fac1 + ts1;

#pragma unroll
        for (int t = 0; t < 16; t++) {
            o[t][0] *= fac0; o[t][1] *= fac0;
            o[t][2] *= fac1; o[t][3] *= fac1;
        }

        // ---- O += P V (3 split passes), P from registers ----
#pragma unroll
        for (int kk = 0; kk < 8; kk++) {
            uint32_t ah[4], al[4];
            split2(s[2 * kk][0],     s[2 * kk][1],     ah[0], al[0]);
            split2(s[2 * kk][2],     s[2 * kk][3],     ah[1], al[1]);
            split2(s[2 * kk + 1][0], s[2 * kk + 1][1], ah[2], al[2]);
            split2(s[2 * kk + 1][2], s[2 * kk + 1][3], ah[3], al[3]);
#pragma unroll
            for (int nt = 0; nt < 8; nt++) {
                uint32_t vf[4], vg[4];
                uint32_t voff = ((kk * 16 + v_r) * SK + nt * 16 + v_c8 * 8) * 2;
                ldsm_x4_t(vf, sVh + voff);
                ldsm_x4_t(vg, sVl + voff);
                mma_bf16(o[2 * nt], ah, vf);
                mma_bf16(o[2 * nt], ah, vg);
                mma_bf16(o[2 * nt], al, vf);
                mma_bf16(o[2 * nt + 1], ah, vf + 2);
                mma_bf16(o[2 * nt + 1], ah, vg + 2);
                mma_bf16(o[2 * nt + 1], al, vf + 2);
            }
        }
        __syncthreads();
    }

    // epilogue: normalize, split, write to out-GEMM inputs
    const int b = bh >> 4, h = bh & 15;
    const int n0 = qt * 128 + wid * 16 + (lane >> 2);
    const float inv0 = 1.0f / lrow0, inv1 = 1.0f / lrow1;
    const size_t grow0 = (size_t)(b * NN + n0) * DIMM;
    const size_t grow1 = (size_t)(b * NN + n0 + 8) * DIMM;
#pragma unroll
    for (int t = 0; t < 16; t++) {
        int col = h * HDIM + t * 8 + (lane & 3) * 2;
        uint32_t hi0, lo0, hi1, lo1;
        split2(o[t][0] * inv0, o[t][1] * inv0, hi0, lo0);
        split2(o[t][2] * inv1, o[t][3] * inv1, hi1, lo1);
        *(uint32_t*)(Ohi + grow0 + col) = hi0;
        *(uint32_t*)(Olo + grow0 + col) = lo0;
        *(uint32_t*)(Ohi + grow1 + col) = hi1;
        *(uint32_t*)(Olo + grow1 + col) = lo1;
    }
}

// ============================================================================
// Launch
// ============================================================================
extern "C" void kernel_launch(void* const* d_in, const int* in_sizes, int n_in,
                              void* d_out, int out_size)
{
    const float* x     = (const float*)d_in[0];
    const float* Wqkv  = (const float*)d_in[1];
    const float* qg    = (const float*)d_in[2];
    const float* kg    = (const float*)d_in[3];
    const float* Wout  = (const float*)d_in[4];
    const float* freqs = (const float*)d_in[5];
    float* out = (float*)d_out;

    float* qkv;
    __nv_bfloat16 *qhi, *qlo, *khi, *klo, *vhi, *vlo;
    __nv_bfloat16 *xhi, *xlo, *w1hi, *w1lo, *w2hi, *w2lo, *aohi, *aolo;
    cudaGetSymbolAddress((void**)&qkv, g_qkv);
    cudaGetSymbolAddress((void**)&qhi, g_qhi);
    cudaGetSymbolAddress((void**)&qlo, g_qlo);
    cudaGetSymbolAddress((void**)&khi, g_khi);
    cudaGetSymbolAddress((void**)&klo, g_klo);
    cudaGetSymbolAddress((void**)&vhi, g_vhi);
    cudaGetSymbolAddress((void**)&vlo, g_vlo);
    cudaGetSymbolAddress((void**)&xhi, g_xhi);
    cudaGetSymbolAddress((void**)&xlo, g_xlo);
    cudaGetSymbolAddress((void**)&w1hi, g_w1hi);
    cudaGetSymbolAddress((void**)&w1lo, g_w1lo);
    cudaGetSymbolAddress((void**)&w2hi, g_w2hi);
    cudaGetSymbolAddress((void**)&w2lo, g_w2lo);
    cudaGetSymbolAddress((void**)&aohi, g_aohi);
    cudaGetSymbolAddress((void**)&aolo, g_aolo);

    cudaFuncSetAttribute(gemm_mma_split,
                         cudaFuncAttributeMaxDynamicSharedMemorySize, GEMM_SMEM);
    cudaFuncSetAttribute(attn_mma,
                         cudaFuncAttributeMaxDynamicSharedMemorySize, ATT_SMEM);

    // splits of inputs
    {
        int n4x = (MROWS * DIMM) / 4;
        split_bf16<<<n4x / 256, 256>>>(x, xhi, xlo, n4x);
        int n4w1 = (E3 * DIMM) / 4;
        split_bf16<<<n4w1 / 256, 256>>>(Wqkv, w1hi, w1lo, n4w1);
        int n4w2 = (DIMM * DIMM) / 4;
        split_bf16<<<n4w2 / 256, 256>>>(Wout, w2hi, w2lo, n4w2);
    }
    // 1. QKV GEMM
    {
        dim3 grid(E3 / 128, MROWS / 128);
        gemm_mma_split<<<grid, 256, GEMM_SMEM>>>(xhi, xlo, w1hi, w1lo, qkv, E3, DIMM);
    }
    // 2. RMSNorm + RoPE + scatter (emits bf16 hi/lo q,k,v)
    norm_rope_scatter<<<MROWS * HN, 128>>>(qkv, qg, kg, freqs);
    // 3. Attention (emits bf16 hi/lo attention output)
    attn_mma<<<BB * HN * 16, 256, ATT_SMEM>>>(qhi, qlo, khi, klo, vhi, vlo,
                                              aohi, aolo);
    // 4. out GEMM
    {
        dim3 grid(DIMM / 128, MROWS / 128);
        gemm_mma_split<<<grid, 256, GEMM_SMEM>>>(aohi, aolo, w2hi, w2lo, out, DIMM, DIMM);
    }
}